// round 10
// baseline (speedup 1.0000x reference)
#include <cuda_runtime.h>
#include <cuda_bf16.h>
#include <cstdint>

// Problem constants
#define N_SAMPLES    65536
#define START_SIZE   4096
#define N_EVENTS     32
#define ROW_F4       (N_SAMPLES / 4)          // 16384 float4 per row
#define SEGS_PER_ROW 8
#define SEG_F4       (ROW_F4 / SEGS_PER_ROW)  // 2048 float4 per segment
#define THREADS      256
#define F4_PER_THR   (SEG_F4 / THREADS)       // 8
#define POS_F4       (START_SIZE / 4)         // 1024 float4 per event
#define POS_ITERS    (POS_F4 / THREADS)       // 4
#define NWARPS       (THREADS / 32)           // 8
#define SLOT_STRIDE  32                       // 128B pad per event slot

// Per-event shift slot, value = d4+1 (0 = not ready). 128B padded.
// Zero-initialized at load; the in-kernel reset maintains the invariant
// across graph replays.
__device__ int g_shift[N_EVENTS * SLOT_STRIDE];
__device__ unsigned g_done = 0;

__global__ void __launch_bounds__(THREADS)
fused_shift_kernel(const float4* __restrict__ in,
                   const float4* __restrict__ pos,
                   float4* __restrict__ out)
{
    const int bid = blockIdx.x;
    const int tid = threadIdx.x;
    const int row = bid >> 3;                   // bid / SEGS_PER_ROW
    const int seg = bid & (SEGS_PER_ROW - 1);
    const int e   = row & (N_EVENTS - 1);
    const size_t rbase = (size_t)row * ROW_F4;
    const int j0 = seg * SEG_F4 + tid;
    const float4* src_base = in + rbase + j0;

    // ---- Producers: blocks 0..31 compute argmax for event==bid (ONCE) ----
    if (bid < N_EVENTS) {
        const float4* p4 = pos + (size_t)bid * POS_F4;
        float    bv = __int_as_float(0xff800000);   // -inf
        unsigned bi = 0u;
        #pragma unroll
        for (int kk = 0; kk < POS_ITERS; kk++) {
            const int i4 = tid + kk * THREADS;
            const float4 v = p4[i4];
            const unsigned b = (unsigned)(i4 * 4);
            // jnp.argmax first-index tie rule: ascending order, strict '>'
            if (v.x > bv) { bv = v.x; bi = b + 0u; }
            if (v.y > bv) { bv = v.y; bi = b + 1u; }
            if (v.z > bv) { bv = v.z; bi = b + 2u; }
            if (v.w > bv) { bv = v.w; bi = b + 3u; }
        }
        #pragma unroll
        for (int off = 16; off > 0; off >>= 1) {
            const float    ov = __shfl_down_sync(0xFFFFFFFFu, bv, off);
            const unsigned oi = __shfl_down_sync(0xFFFFFFFFu, bi, off);
            if (ov > bv || (ov == bv && oi < bi)) { bv = ov; bi = oi; }
        }
        __shared__ float    s_v[NWARPS];
        __shared__ unsigned s_i[NWARPS];
        if ((tid & 31) == 0) { s_v[tid >> 5] = bv; s_i[tid >> 5] = bi; }
        __syncthreads();
        if (tid == 0) {
            float    cv = s_v[0];
            unsigned ci = s_i[0];
            #pragma unroll
            for (int w = 1; w < NWARPS; w++) {
                const float ov = s_v[w];
                const unsigned oi = s_i[w];
                if (ov > cv || (ov == cv && oi < ci)) { cv = ov; ci = oi; }
            }
            const int d4p = (int)ci * 4;            // STEP=16 floats = 4 f4
            asm volatile("st.release.gpu.global.u32 [%0], %1;"
                         :: "l"(&g_shift[bid * SLOT_STRIDE]), "r"(d4p + 1)
                         : "memory");
        }
    }

    // ---- Phase 1: issue all copy loads (shift-independent) ---------------
    float4 vals[F4_PER_THR];
    #pragma unroll
    for (int k = 0; k < F4_PER_THR; k++)
        vals[k] = src_base[k * THREADS];

    // ---- Phase 2: fetch this row's shift (poll overlaps load latency) ----
    __shared__ int s_d4;
    if (tid == 0) {
        unsigned v;
        asm volatile("ld.acquire.gpu.global.u32 %0, [%1];"
                     : "=r"(v) : "l"(&g_shift[e * SLOT_STRIDE]) : "memory");
        while (v == 0u) {
            __nanosleep(40);
            asm volatile("ld.acquire.gpu.global.u32 %0, [%1];"
                         : "=r"(v) : "l"(&g_shift[e * SLOT_STRIDE]) : "memory");
        }
        s_d4 = (int)v - 1;
    }
    __syncthreads();
    const int d4 = s_d4;

    // ---- Phase 3: shifted streaming stores. out[(j+d4) mod ROW_F4] -------
    // jp < ROW_F4 -> in[j] ; jp >= ROW_F4 -> 0 (bijective head-zeroing)
    float4* dst_base = out + rbase;
    const float4 zero = make_float4(0.f, 0.f, 0.f, 0.f);
    #pragma unroll
    for (int k = 0; k < F4_PER_THR; k++) {
        const int jp = j0 + k * THREADS + d4;
        if (jp < ROW_F4) {
            __stcs(dst_base + jp, vals[k]);
        } else {
            __stcs(dst_base + jp - ROW_F4, zero);
        }
    }

    // ---- Phase 4: last finishing block resets slots (replay-safe) --------
    __syncthreads();                 // all reads of g_shift in this block done
    if (tid == 0) {
        const unsigned old = atomicAdd(&g_done, 1u);
        if (old == gridDim.x - 1) {  // every other block has read its slot
            #pragma unroll
            for (int i = 0; i < N_EVENTS; i++)
                g_shift[i * SLOT_STRIDE] = 0;
            atomicExch(&g_done, 0u);
        }
    }
}

extern "C" void kernel_launch(void* const* d_in, const int* in_sizes, int n_in,
                              void* d_out, int out_size) {
    const float* events = (const float*)d_in[0];   // (B, 32, 65536) f32
    const float* pos    = (const float*)d_in[1];   // (1, 32, 4096)  f32

    const int batch = in_sizes[0] / (N_EVENTS * N_SAMPLES);   // 8
    const int rows  = batch * N_EVENTS;                       // 256
    const int grid  = rows * SEGS_PER_ROW;                    // 2048

    fused_shift_kernel<<<grid, THREADS>>>((const float4*)events,
                                          (const float4*)pos,
                                          (float4*)d_out);
}

// round 11
// speedup vs baseline: 1.1723x; 1.1723x over previous
#include <cuda_runtime.h>
#include <cuda_bf16.h>
#include <cstdint>

// Problem constants
#define N_SAMPLES    65536
#define START_SIZE   4096
#define N_EVENTS     32
#define ROW_F4       (N_SAMPLES / 4)          // 16384 float4 per row
#define SEGS_PER_ROW 2
#define SEG_F4       (ROW_F4 / SEGS_PER_ROW)  // 8192 float4 per segment
#define THREADS      512
#define F4_PER_THR   (SEG_F4 / THREADS)       // 16
#define POS_F4       (START_SIZE / 4)         // 1024 float4 per event
#define POS_ITERS    (POS_F4 / THREADS)       // 2
#define NWARPS       (THREADS / 32)           // 16
#define CHUNK        4                        // float4 live per copy wave
#define NCHUNK       (F4_PER_THR / CHUNK)     // 4

__global__ void __launch_bounds__(THREADS)
fused_shift_kernel(const float4* __restrict__ in,
                   const float4* __restrict__ pos,
                   float4* __restrict__ out)
{
    const int bid = blockIdx.x;
    const int tid = threadIdx.x;
    const int row = bid >> 1;                   // bid / SEGS_PER_ROW
    const int seg = bid & (SEGS_PER_ROW - 1);
    const int e   = row & (N_EVENTS - 1);
    const size_t rbase = (size_t)row * ROW_F4;
    const int j0 = seg * SEG_F4 + tid;
    const float4* src_base = in + rbase + j0;
    float4* dst_base = out + rbase;

    // ---- Phase 0a: pos loads first (heads the L1tex queue) ---------------
    const float4* p4 = pos + (size_t)e * POS_F4;
    float4 pv[POS_ITERS];
    #pragma unroll
    for (int kk = 0; kk < POS_ITERS; kk++)
        pv[kk] = p4[tid + kk * THREADS];

    // ---- Phase 0b: chunk-0 copy loads (overlap argmax latency) -----------
    float4 v[CHUNK];
    #pragma unroll
    for (int k = 0; k < CHUNK; k++)
        v[k] = src_base[k * THREADS];

    // ---- Phase 1: single-pass argmax (jnp first-index tie rule) ----------
    float    bv = __int_as_float(0xff800000);   // -inf
    unsigned bi = 0u;
    #pragma unroll
    for (int kk = 0; kk < POS_ITERS; kk++) {
        const unsigned b = (unsigned)((tid + kk * THREADS) * 4);
        const float4 pvv = pv[kk];
        if (pvv.x > bv) { bv = pvv.x; bi = b + 0u; }
        if (pvv.y > bv) { bv = pvv.y; bi = b + 1u; }
        if (pvv.z > bv) { bv = pvv.z; bi = b + 2u; }
        if (pvv.w > bv) { bv = pvv.w; bi = b + 3u; }
    }
    #pragma unroll
    for (int off = 16; off > 0; off >>= 1) {
        const float    ov = __shfl_down_sync(0xFFFFFFFFu, bv, off);
        const unsigned oi = __shfl_down_sync(0xFFFFFFFFu, bi, off);
        if (ov > bv || (ov == bv && oi < bi)) { bv = ov; bi = oi; }
    }

    __shared__ float    s_v[NWARPS];
    __shared__ unsigned s_i[NWARPS];
    __shared__ int s_d4;
    if ((tid & 31) == 0) { s_v[tid >> 5] = bv; s_i[tid >> 5] = bi; }
    __syncthreads();
    if (tid == 0) {
        float    cv = s_v[0];
        unsigned ci = s_i[0];
        #pragma unroll
        for (int w = 1; w < NWARPS; w++) {
            const float ov = s_v[w];
            const unsigned oi = s_i[w];
            if (ov > cv || (ov == cv && oi < ci)) { cv = ov; ci = oi; }
        }
        s_d4 = (int)ci * 4;                   // STEP=16 floats = 4 float4
    }
    __syncthreads();
    const int d4 = s_d4;

    // ---- Phase 2: pipelined shifted copy: store chunk c, load chunk c+1 --
    // out[(j+d4) mod ROW_F4]: jp < ROW_F4 -> in[j], else 0 (head zeroing).
    const float4 zero = make_float4(0.f, 0.f, 0.f, 0.f);
    #pragma unroll
    for (int c = 0; c < NCHUNK; c++) {
        float4 nv[CHUNK];
        if (c + 1 < NCHUNK) {                 // prefetch next chunk's loads
            #pragma unroll
            for (int k = 0; k < CHUNK; k++)
                nv[k] = src_base[((c + 1) * CHUNK + k) * THREADS];
        }
        #pragma unroll
        for (int k = 0; k < CHUNK; k++) {
            const int jp = j0 + (c * CHUNK + k) * THREADS + d4;
            if (jp < ROW_F4) {
                __stcs(dst_base + jp, v[k]);
            } else {
                __stcs(dst_base + jp - ROW_F4, zero);
            }
        }
        #pragma unroll
        for (int k = 0; k < CHUNK; k++) v[k] = nv[k];
    }
}

extern "C" void kernel_launch(void* const* d_in, const int* in_sizes, int n_in,
                              void* d_out, int out_size) {
    const float* events = (const float*)d_in[0];   // (B, 32, 65536) f32
    const float* pos    = (const float*)d_in[1];   // (1, 32, 4096)  f32

    const int batch = in_sizes[0] / (N_EVENTS * N_SAMPLES);   // 8
    const int rows  = batch * N_EVENTS;                       // 256
    const int grid  = rows * SEGS_PER_ROW;                    // 512

    fused_shift_kernel<<<grid, THREADS>>>((const float4*)events,
                                          (const float4*)pos,
                                          (float4*)d_out);
}